// round 11
// baseline (speedup 1.0000x reference)
#include <cuda_runtime.h>
#include <stdint.h>

#define NMAX 50000
#define EMAX 1600000
#define NG   3
#define NH   9
#define HCc  72
#define HROW 96          // 72 feat + 9 a_src + pad -> 384B = 3 x 128B lines
#define PAD  12
#define NEG_SLOPE 0.2f
#define SCAN_CHUNK 1024

// ---------------- device scratch (3 graphs batched, virtual id = g*N + node) --
__device__ __align__(128) float g_h[(size_t)NG * NMAX * HROW];
__device__ __align__(16)  float g_ad[NG * NMAX * PAD];
__device__ __align__(16)  float g_concat[NMAX * NG * HCc];   // [N,216]
__device__ int g_src[NG * EMAX];
__device__ int g_dst[NG * EMAX];
__device__ int g_deg[NG * NMAX];
__device__ int g_off[NG * NMAX + 1];
__device__ int g_cursor[NG * NMAX];
__device__ int g_csr[NG * EMAX];
__device__ int g_bsum[256];
__device__ int g_bofs[256];
__device__ int g_is64;

__device__ __forceinline__ float lrelu(float x) {
    return x > 0.f ? x : NEG_SLOPE * x;
}

// ---------------- K0a: detect edge_index dtype --------------------------------
__global__ void k_detect(const int* __restrict__ ei32, int E) {
    __shared__ int ok;
    int t = threadIdx.x;
    if (t == 0) ok = 1;
    __syncthreads();
    int cnt = E < 512 ? E : 512;
    bool z = true;
    for (int i = t; i < cnt; i += blockDim.x)
        if (ei32[2 * i + 1] != 0) z = false;
    if (!z) ok = 0;
    __syncthreads();
    if (t == 0) g_is64 = ok;
}

// ---------------- K0b: zero degree counters ------------------------------------
__global__ void k_zero(int n3) {
    int i = blockIdx.x * blockDim.x + threadIdx.x;
    if (i < n3) g_deg[i] = 0;
}

// ---------------- K0c: decode + clamp, histogram (blockIdx.y = graph) ----------
__global__ void k_convert_hist(const int* __restrict__ e0,
                               const int* __restrict__ e1,
                               const int* __restrict__ e2, int E, int n) {
    int le = blockIdx.x * blockDim.x + threadIdx.x;
    if (le >= E) return;
    int g = blockIdx.y;
    const int* ei32 = (g == 0) ? e0 : (g == 1) ? e1 : e2;
    long long s, d;
    if (g_is64) {
        const long long* p = (const long long*)ei32;
        s = p[le]; d = p[(size_t)E + le];
    } else {
        s = ei32[le]; d = ei32[(size_t)E + le];
    }
    if (s < 0 || s >= n) s = 0;
    if (d < 0 || d >= n) d = 0;
    int vs = (int)s + g * n, vd = (int)d + g * n;
    size_t ve = (size_t)g * E + le;
    g_src[ve] = vs;
    g_dst[ve] = vd;
    atomicAdd(&g_deg[vd], 1);
}

// ---------------- K0d: 3-phase multi-block exclusive scan ----------------------
__global__ void k_scan_a(int n3) {
    int base = blockIdx.x * SCAN_CHUNK;
    int t = threadIdx.x;
    int s = 0;
    for (int i = t; i < SCAN_CHUNK; i += 256) {
        int idx = base + i;
        if (idx < n3) s += g_deg[idx];
    }
    __shared__ int red[256];
    red[t] = s;
    __syncthreads();
    for (int o = 128; o; o >>= 1) {
        if (t < o) red[t] += red[t + o];
        __syncthreads();
    }
    if (t == 0) g_bsum[blockIdx.x] = red[0];
}
__global__ void k_scan_b(int B) {
    __shared__ int sm[256];
    int t = threadIdx.x;
    sm[t] = (t < B) ? g_bsum[t] : 0;
    __syncthreads();
    for (int o = 1; o < 256; o <<= 1) {
        int v = (t >= o) ? sm[t - o] : 0;
        __syncthreads();
        sm[t] += v;
        __syncthreads();
    }
    if (t < B) g_bofs[t] = (t == 0) ? 0 : sm[t - 1];
}
__global__ void k_scan_c(int n3) {
    int base = blockIdx.x * SCAN_CHUNK;
    int t = threadIdx.x;
    int v[4], s = 0;
    #pragma unroll
    for (int k = 0; k < 4; k++) {
        int idx = base + 4 * t + k;
        v[k] = (idx < n3) ? g_deg[idx] : 0;
        s += v[k];
    }
    __shared__ int sm[256];
    sm[t] = s;
    __syncthreads();
    for (int o = 1; o < 256; o <<= 1) {
        int x = (t >= o) ? sm[t - o] : 0;
        __syncthreads();
        sm[t] += x;
        __syncthreads();
    }
    int run = g_bofs[blockIdx.x] + ((t == 0) ? 0 : sm[t - 1]);
    #pragma unroll
    for (int k = 0; k < 4; k++) {
        int idx = base + 4 * t + k;
        if (idx < n3) {
            g_off[idx] = run;
            g_cursor[idx] = run;
            run += v[k];
            if (idx == n3 - 1) g_off[n3] = run;
        }
    }
}

// ---------------- K0e: scatter src ids into CSR slots --------------------------
__global__ void k_fill(int E3) {
    int e = blockIdx.x * blockDim.x + threadIdx.x;
    if (e >= E3) return;
    int d = g_dst[e];
    int pos = atomicAdd(&g_cursor[d], 1);
    g_csr[pos] = g_src[e];
}

// ---------------- K1: h = x @ W, batched ---------------------------------------
__global__ __launch_bounds__(288) void k_linear(
        const float* __restrict__ x0, const float* __restrict__ x1,
        const float* __restrict__ x2,
        const float* __restrict__ W0, const float* __restrict__ W1,
        const float* __restrict__ W2, int n) {
    int g = blockIdx.y;
    const float* x = (g == 0) ? x0 : (g == 1) ? x1 : x2;
    const float* W = (g == 0) ? W0 : (g == 1) ? W1 : W2;
    __shared__ float Ws[128 * HCc];
    __shared__ float xs[16][128];
    int t = threadIdx.x;
    for (int i = t; i < 128 * HCc; i += 288) Ws[i] = W[i];
    int base = blockIdx.x * 16;
    for (int i = t; i < 16 * 128; i += 288) {
        int r = i >> 7, k = i & 127;
        xs[r][k] = (base + r < n) ? x[(size_t)(base + r) * 128 + k] : 0.f;
    }
    __syncthreads();
    int col = t % HCc;
    int r0  = t / HCc;
    #pragma unroll
    for (int rr = 0; rr < 4; rr++) {
        int r = rr * 4 + r0;
        int node = base + r;
        if (node < n) {
            float acc = 0.f;
            #pragma unroll 16
            for (int k = 0; k < 128; k++) acc += xs[r][k] * Ws[k * HCc + col];
            g_h[((size_t)g * n + node) * HROW + col] = acc;
        }
    }
}

// ---------------- K2: attention scalars, batched --------------------------------
__global__ void k_scores(const float* __restrict__ s0, const float* __restrict__ s1,
                         const float* __restrict__ s2,
                         const float* __restrict__ d0, const float* __restrict__ d1,
                         const float* __restrict__ d2, int n) {
    int i = blockIdx.x * blockDim.x + threadIdx.x;
    if (i >= n * NH) return;
    int g = blockIdx.y;
    const float* att_s = (g == 0) ? s0 : (g == 1) ? s1 : s2;
    const float* att_d = (g == 0) ? d0 : (g == 1) ? d1 : d2;
    int node = i / NH, hh = i % NH;
    size_t v = (size_t)g * n + node;
    const float* hp = g_h + v * HROW + hh * 8;
    float as = 0.f, ad = 0.f;
    #pragma unroll
    for (int c = 0; c < 8; c++) {
        float vv = hp[c];
        as += vv * att_s[hh * 8 + c];
        ad += vv * att_d[hh * 8 + c];
    }
    g_h[v * HROW + 72 + hh] = as;
    g_ad[v * PAD + hh] = ad;
}

// ---------------- K3: warp-per-dst GAT, aligned rows + prefetch pipeline --------
__global__ __launch_bounds__(256) void k_gat(
        const float* __restrict__ b0, const float* __restrict__ b1,
        const float* __restrict__ b2, int n) {
    __shared__ float sw[8][32][13];
    __shared__ int   si[8][32];
    int gwarp = (blockIdx.x * 256 + threadIdx.x) >> 5;
    int lane  = threadIdx.x & 31;
    int wib   = threadIdx.x >> 5;
    if (gwarp >= n) return;
    int g = blockIdx.y;
    const float* bias = (g == 0) ? b0 : (g == 1) ? b1 : b2;
    int d = g * n + gwarp;
    int beg = g_off[d], end = g_off[d + 1];

    const float* hd = g_h + (size_t)d * HROW;
    float ad_r[NH], aself_w[NH];
    #pragma unroll
    for (int h = 0; h < NH; h++) {
        ad_r[h]    = g_ad[(size_t)d * PAD + h];
        aself_w[h] = __expf(lrelu(hd[72 + h] + ad_r[h]));
    }
    int h1 = lane >> 3;
    int h2 = (lane + 32) >> 3;

    float dsum[NH];
    #pragma unroll
    for (int h = 0; h < NH; h++) dsum[h] = 0.f;

    float acc1a = aself_w[h1] * hd[lane],      acc1b = 0.f;
    float acc2a = aself_w[h2] * hd[lane + 32], acc2b = 0.f;
    float acc3a = (lane < 8) ? aself_w[8] * hd[lane + 64] : 0.f, acc3b = 0.f;

    // prologue: prefetch chunk 0 (csr index + 9 src scores) into registers
    int   s_n = 0, ecnt_n = 0;
    float4 q0 = make_float4(0.f, 0.f, 0.f, 0.f);
    float4 q1 = q0;
    float  q8 = 0.f;
    if (beg < end) {
        ecnt_n = min(32, end - beg);
        if (lane < ecnt_n) {
            s_n = g_csr[beg + lane];
            const float* sc = g_h + (size_t)s_n * HROW + 72;
            q0 = *(const float4*)(sc);
            q1 = *(const float4*)(sc + 4);
            q8 = sc[8];
        }
    }

    for (int cbeg = beg; cbeg < end; cbeg += 32) {
        int ecnt = ecnt_n;
        int s_mine = s_n;
        float wv[NH];
        {
            float asv[NH] = {q0.x, q0.y, q0.z, q0.w, q1.x, q1.y, q1.z, q1.w, q8};
            if (lane < ecnt) {
                #pragma unroll
                for (int h = 0; h < NH; h++) {
                    wv[h] = __expf(lrelu(asv[h] + ad_r[h]));
                    dsum[h] += wv[h];
                }
            } else {
                #pragma unroll
                for (int h = 0; h < NH; h++) wv[h] = 0.f;
            }
        }
        #pragma unroll
        for (int h = 0; h < NH; h++) sw[wib][lane][h] = wv[h];
        si[wib][lane] = s_mine;
        __syncwarp();

        // prefetch NEXT chunk while the sweep below hides the latency
        int nb = cbeg + 32;
        if (nb < end) {
            ecnt_n = min(32, end - nb);
            if (lane < ecnt_n) {
                s_n = g_csr[nb + lane];
                const float* sc = g_h + (size_t)s_n * HROW + 72;
                q0 = *(const float4*)(sc);
                q1 = *(const float4*)(sc + 4);
                q8 = sc[8];
            }
        }

        // feature-parallel sweep, 4 edges/iter, loads batched up front
        int j = 0;
        for (; j + 4 <= ecnt; j += 4) {
            const float* p0 = g_h + (size_t)si[wib][j + 0] * HROW;
            const float* p1 = g_h + (size_t)si[wib][j + 1] * HROW;
            const float* p2 = g_h + (size_t)si[wib][j + 2] * HROW;
            const float* p3 = g_h + (size_t)si[wib][j + 3] * HROW;
            float a0 = p0[lane],      a1 = p1[lane],      a2 = p2[lane],      a3 = p3[lane];
            float c0 = p0[lane + 32], c1 = p1[lane + 32], c2 = p2[lane + 32], c3 = p3[lane + 32];
            float e0 = 0.f, e1 = 0.f, e2 = 0.f, e3 = 0.f;
            if (lane < 8) {
                e0 = p0[lane + 64]; e1 = p1[lane + 64];
                e2 = p2[lane + 64]; e3 = p3[lane + 64];
            }
            float w10 = sw[wib][j + 0][h1], w11 = sw[wib][j + 1][h1];
            float w12 = sw[wib][j + 2][h1], w13 = sw[wib][j + 3][h1];
            float w20 = sw[wib][j + 0][h2], w21 = sw[wib][j + 1][h2];
            float w22 = sw[wib][j + 2][h2], w23 = sw[wib][j + 3][h2];
            acc1a += w10 * a0; acc1b += w11 * a1;
            acc1a += w12 * a2; acc1b += w13 * a3;
            acc2a += w20 * c0; acc2b += w21 * c1;
            acc2a += w22 * c2; acc2b += w23 * c3;
            if (lane < 8) {
                float w30 = sw[wib][j + 0][8], w31 = sw[wib][j + 1][8];
                float w32 = sw[wib][j + 2][8], w33 = sw[wib][j + 3][8];
                acc3a += w30 * e0; acc3b += w31 * e1;
                acc3a += w32 * e2; acc3b += w33 * e3;
            }
        }
        for (; j < ecnt; j++) {
            const float* p = g_h + (size_t)si[wib][j] * HROW;
            acc1a += sw[wib][j][h1] * p[lane];
            acc2a += sw[wib][j][h2] * p[lane + 32];
            if (lane < 8) acc3a += sw[wib][j][8] * p[lane + 64];
        }
        __syncwarp();
    }

    float acc1 = acc1a + acc1b, acc2 = acc2a + acc2b, acc3 = acc3a + acc3b;

    #pragma unroll
    for (int h = 0; h < NH; h++) {
        float v = dsum[h];
        #pragma unroll
        for (int ofs = 16; ofs; ofs >>= 1) v += __shfl_xor_sync(0xffffffffu, v, ofs);
        dsum[h] = v + aself_w[h];
    }

    float* orow = g_concat + (size_t)gwarp * (NG * HCc) + g * HCc;
    orow[lane]      = acc1 / (dsum[h1] + 1e-16f) + bias[lane];
    orow[lane + 32] = acc2 / (dsum[h2] + 1e-16f) + bias[lane + 32];
    if (lane < 8)
        orow[lane + 64] = acc3 / (dsum[8] + 1e-16f) + bias[lane + 64];
}

// ---------------- K4: relu -> [216,2] FNN -> softmax ----------------------------
__global__ void k_fnn(const float* __restrict__ fW, const float* __restrict__ fb,
                      float* __restrict__ out, int n) {
    __shared__ float Wl[NG * HCc * 2];
    int t = threadIdx.x;
    for (int i = t; i < NG * HCc * 2; i += blockDim.x) Wl[i] = fW[i];
    __syncthreads();
    int node = blockIdx.x * blockDim.x + t;
    if (node >= n) return;
    const float* row = g_concat + (size_t)node * (NG * HCc);
    float l0 = fb[0], l1 = fb[1];
    #pragma unroll 8
    for (int i = 0; i < NG * HCc; i++) {
        float v = row[i];
        v = v > 0.f ? v : 0.f;
        l0 += v * Wl[2 * i];
        l1 += v * Wl[2 * i + 1];
    }
    float mm = fmaxf(l0, l1);
    float e0 = __expf(l0 - mm), e1 = __expf(l1 - mm);
    float inv = 1.f / (e0 + e1);
    out[2 * node]     = e0 * inv;
    out[2 * node + 1] = e1 * inv;
}

// ---------------- host -----------------------------------------------------------
extern "C" void kernel_launch(void* const* d_in, const int* in_sizes, int n_in,
                              void* d_out, int out_size) {
    const float* x[3]   = {0, 0, 0};
    const int*   ei[3]  = {0, 0, 0};
    const float* W[3]   = {0, 0, 0};
    const float* asr[3] = {0, 0, 0};
    const float* adr[3] = {0, 0, 0};
    const float* b[3]   = {0, 0, 0};
    const float* fW = 0; const float* fb = 0;
    int ix = 0, ie = 0, iw = 0, cur = 0, c72 = 0;
    long long xsz = 0, esz = 0;

    for (int i = 0; i < n_in; i++) {
        long long sz = in_sizes[i];
        if (sz >= 1000000) {
            if (sz > 4000000) {
                if (ix < 3) { x[ix++] = (const float*)d_in[i]; xsz = sz; }
            } else {
                if (ie < 3) { ei[ie++] = (const int*)d_in[i]; esz = sz; }
            }
        } else if (sz == 128 * HCc) {
            if (iw < 3) { W[iw] = (const float*)d_in[i]; cur = iw; iw++; c72 = 0; }
        } else if (sz == HCc) {
            if (c72 == 0)      asr[cur] = (const float*)d_in[i];
            else if (c72 == 1) adr[cur] = (const float*)d_in[i];
            else               b[cur]   = (const float*)d_in[i];
            c72++;
        } else if (sz == NG * HCc * 2) {
            fW = (const float*)d_in[i];
        } else if (sz == 2) {
            fb = (const float*)d_in[i];
        }
    }

    int N = (int)(xsz / 128);
    int E = (int)(esz / 2);
    int n3 = NG * N, E3 = NG * E;
    float* out = (float*)d_out;

    dim3 gE((E + 255) / 256, NG);
    dim3 gLin((N + 15) / 16, NG);
    dim3 gSc((N * NH + 255) / 256, NG);
    dim3 gGat((N + 7) / 8, NG);
    int bN3 = (n3 + 255) / 256;
    int bE3 = (E3 + 255) / 256;
    int B = (n3 + SCAN_CHUNK - 1) / SCAN_CHUNK;

    k_detect      <<<1, 256>>>(ei[0], E);
    k_zero        <<<bN3, 256>>>(n3);
    k_convert_hist<<<gE, 256>>>(ei[0], ei[1], ei[2], E, N);
    k_scan_a      <<<B, 256>>>(n3);
    k_scan_b      <<<1, 256>>>(B);
    k_scan_c      <<<B, 256>>>(n3);
    k_fill        <<<bE3, 256>>>(E3);
    k_linear      <<<gLin, 288>>>(x[0], x[1], x[2], W[0], W[1], W[2], N);
    k_scores      <<<gSc, 256>>>(asr[0], asr[1], asr[2], adr[0], adr[1], adr[2], N);
    k_gat         <<<gGat, 256>>>(b[0], b[1], b[2], N);
    k_fnn         <<<(N + 255) / 256, 256>>>(fW, fb, out, N);
    (void)out_size;
}

// round 12
// speedup vs baseline: 1.5591x; 1.5591x over previous
#include <cuda_runtime.h>
#include <stdint.h>

#define NMAX 50000
#define EMAX 1600000
#define NG   3
#define NH   9
#define HCc  72
#define HROW 96          // 72 feat + 9 a_src + pad -> 384B = 3 x 128B lines
#define PAD  12
#define NEG_SLOPE 0.2f
#define SCAN_CHUNK 1024

// ---------------- device scratch (3 graphs batched, virtual id = g*N + node) --
__device__ __align__(128) float g_h[(size_t)NG * NMAX * HROW];
__device__ __align__(16)  float g_ad[NG * NMAX * PAD];
__device__ __align__(16)  float g_concat[NMAX * NG * HCc];   // [N,216]
__device__ int g_src[NG * EMAX];
__device__ int g_dst[NG * EMAX];
__device__ int g_deg[NG * NMAX];
__device__ int g_off[NG * NMAX + 1];
__device__ int g_cursor[NG * NMAX];
__device__ int g_csr[NG * EMAX];
__device__ int g_bsum[256];
__device__ int g_bofs[256];
__device__ int g_is64;

__device__ __forceinline__ float lrelu(float x) {
    return x > 0.f ? x : NEG_SLOPE * x;
}

// ---------------- K0a: detect edge_index dtype --------------------------------
__global__ void k_detect(const int* __restrict__ ei32, int E) {
    __shared__ int ok;
    int t = threadIdx.x;
    if (t == 0) ok = 1;
    __syncthreads();
    int cnt = E < 512 ? E : 512;
    bool z = true;
    for (int i = t; i < cnt; i += blockDim.x)
        if (ei32[2 * i + 1] != 0) z = false;
    if (!z) ok = 0;
    __syncthreads();
    if (t == 0) g_is64 = ok;
}

// ---------------- K0b: zero degree counters ------------------------------------
__global__ void k_zero(int n3) {
    int i = blockIdx.x * blockDim.x + threadIdx.x;
    if (i < n3) g_deg[i] = 0;
}

// ---------------- K0c: decode + clamp, histogram (blockIdx.y = graph) ----------
__global__ void k_convert_hist(const int* __restrict__ e0,
                               const int* __restrict__ e1,
                               const int* __restrict__ e2, int E, int n) {
    int le = blockIdx.x * blockDim.x + threadIdx.x;
    if (le >= E) return;
    int g = blockIdx.y;
    const int* ei32 = (g == 0) ? e0 : (g == 1) ? e1 : e2;
    long long s, d;
    if (g_is64) {
        const long long* p = (const long long*)ei32;
        s = p[le]; d = p[(size_t)E + le];
    } else {
        s = ei32[le]; d = ei32[(size_t)E + le];
    }
    if (s < 0 || s >= n) s = 0;
    if (d < 0 || d >= n) d = 0;
    int vs = (int)s + g * n, vd = (int)d + g * n;
    size_t ve = (size_t)g * E + le;
    g_src[ve] = vs;
    g_dst[ve] = vd;
    atomicAdd(&g_deg[vd], 1);
}

// ---------------- K0d: 3-phase multi-block exclusive scan ----------------------
__global__ void k_scan_a(int n3) {
    int base = blockIdx.x * SCAN_CHUNK;
    int t = threadIdx.x;
    int s = 0;
    for (int i = t; i < SCAN_CHUNK; i += 256) {
        int idx = base + i;
        if (idx < n3) s += g_deg[idx];
    }
    __shared__ int red[256];
    red[t] = s;
    __syncthreads();
    for (int o = 128; o; o >>= 1) {
        if (t < o) red[t] += red[t + o];
        __syncthreads();
    }
    if (t == 0) g_bsum[blockIdx.x] = red[0];
}
__global__ void k_scan_b(int B) {
    __shared__ int sm[256];
    int t = threadIdx.x;
    sm[t] = (t < B) ? g_bsum[t] : 0;
    __syncthreads();
    for (int o = 1; o < 256; o <<= 1) {
        int v = (t >= o) ? sm[t - o] : 0;
        __syncthreads();
        sm[t] += v;
        __syncthreads();
    }
    if (t < B) g_bofs[t] = (t == 0) ? 0 : sm[t - 1];
}
__global__ void k_scan_c(int n3) {
    int base = blockIdx.x * SCAN_CHUNK;
    int t = threadIdx.x;
    int v[4], s = 0;
    #pragma unroll
    for (int k = 0; k < 4; k++) {
        int idx = base + 4 * t + k;
        v[k] = (idx < n3) ? g_deg[idx] : 0;
        s += v[k];
    }
    __shared__ int sm[256];
    sm[t] = s;
    __syncthreads();
    for (int o = 1; o < 256; o <<= 1) {
        int x = (t >= o) ? sm[t - o] : 0;
        __syncthreads();
        sm[t] += x;
        __syncthreads();
    }
    int run = g_bofs[blockIdx.x] + ((t == 0) ? 0 : sm[t - 1]);
    #pragma unroll
    for (int k = 0; k < 4; k++) {
        int idx = base + 4 * t + k;
        if (idx < n3) {
            g_off[idx] = run;
            g_cursor[idx] = run;
            run += v[k];
            if (idx == n3 - 1) g_off[n3] = run;
        }
    }
}

// ---------------- K0e: scatter src ids into CSR slots --------------------------
__global__ void k_fill(int E3) {
    int e = blockIdx.x * blockDim.x + threadIdx.x;
    if (e >= E3) return;
    int d = g_dst[e];
    int pos = atomicAdd(&g_cursor[d], 1);
    g_csr[pos] = g_src[e];
}

// ---------------- K1: h = x @ W — register-tiled GEMM (4x4 per thread) ---------
// Block tile: 64 rows x 72 cols, K staged in 2 chunks of 64.
// xs transposed [k][row] (pad 65: conflict-free STS, coalesced LDG);
// per k-step: 4 scalar LDS (x) + 1 LDS.128 (W) feed 16 FMA -> 2 B/FMA.
__global__ __launch_bounds__(288) void k_linear(
        const float* __restrict__ x0, const float* __restrict__ x1,
        const float* __restrict__ x2,
        const float* __restrict__ W0, const float* __restrict__ W1,
        const float* __restrict__ W2, int n) {
    int g = blockIdx.y;
    const float* x = (g == 0) ? x0 : (g == 1) ? x1 : x2;
    const float* W = (g == 0) ? W0 : (g == 1) ? W1 : W2;
    __shared__ float xs[64][65];              // 16.6 KB, [k][row]
    __shared__ __align__(16) float Ws[64][72]; // 18 KB,  [k][col]
    int t  = threadIdx.x;
    int cg = t % 18;          // col group: cols 4*cg .. 4*cg+3
    int rg = t / 18;          // row group: rows 4*rg .. 4*rg+3  (0..15)
    int base = blockIdx.x * 64;

    float acc[4][4];
    #pragma unroll
    for (int i = 0; i < 4; i++)
        #pragma unroll
        for (int j = 0; j < 4; j++) acc[i][j] = 0.f;

    for (int kk = 0; kk < 128; kk += 64) {
        for (int i = t; i < 64 * 64; i += 288) {
            int r = i >> 6, k = i & 63;       // consecutive t -> consecutive k
            xs[k][r] = (base + r < n) ? x[(size_t)(base + r) * 128 + kk + k] : 0.f;
        }
        for (int i = t; i < 64 * 72; i += 288) {
            int k = i / 72, c = i - k * 72;
            Ws[k][c] = W[(size_t)(kk + k) * 72 + c];
        }
        __syncthreads();
        #pragma unroll 8
        for (int k = 0; k < 64; k++) {
            float xv0 = xs[k][4 * rg + 0];
            float xv1 = xs[k][4 * rg + 1];
            float xv2 = xs[k][4 * rg + 2];
            float xv3 = xs[k][4 * rg + 3];
            float4 wv = *(const float4*)&Ws[k][4 * cg];
            acc[0][0] += xv0 * wv.x; acc[0][1] += xv0 * wv.y;
            acc[0][2] += xv0 * wv.z; acc[0][3] += xv0 * wv.w;
            acc[1][0] += xv1 * wv.x; acc[1][1] += xv1 * wv.y;
            acc[1][2] += xv1 * wv.z; acc[1][3] += xv1 * wv.w;
            acc[2][0] += xv2 * wv.x; acc[2][1] += xv2 * wv.y;
            acc[2][2] += xv2 * wv.z; acc[2][3] += xv2 * wv.w;
            acc[3][0] += xv3 * wv.x; acc[3][1] += xv3 * wv.y;
            acc[3][2] += xv3 * wv.z; acc[3][3] += xv3 * wv.w;
        }
        __syncthreads();
    }

    #pragma unroll
    for (int i = 0; i < 4; i++) {
        int node = base + 4 * rg + i;
        if (node < n) {
            float4 v = make_float4(acc[i][0], acc[i][1], acc[i][2], acc[i][3]);
            *(float4*)&g_h[((size_t)g * n + node) * HROW + 4 * cg] = v;
        }
    }
}

// ---------------- K2: attention scalars, batched --------------------------------
__global__ void k_scores(const float* __restrict__ s0, const float* __restrict__ s1,
                         const float* __restrict__ s2,
                         const float* __restrict__ d0, const float* __restrict__ d1,
                         const float* __restrict__ d2, int n) {
    int i = blockIdx.x * blockDim.x + threadIdx.x;
    if (i >= n * NH) return;
    int g = blockIdx.y;
    const float* att_s = (g == 0) ? s0 : (g == 1) ? s1 : s2;
    const float* att_d = (g == 0) ? d0 : (g == 1) ? d1 : d2;
    int node = i / NH, hh = i % NH;
    size_t v = (size_t)g * n + node;
    const float* hp = g_h + v * HROW + hh * 8;
    float as = 0.f, ad = 0.f;
    #pragma unroll
    for (int c = 0; c < 8; c++) {
        float vv = hp[c];
        as += vv * att_s[hh * 8 + c];
        ad += vv * att_d[hh * 8 + c];
    }
    g_h[v * HROW + 72 + hh] = as;
    g_ad[v * PAD + hh] = ad;
}

// ---------------- K3: warp-per-dst GAT (R10 body, aligned rows) -----------------
__global__ __launch_bounds__(256) void k_gat(
        const float* __restrict__ b0, const float* __restrict__ b1,
        const float* __restrict__ b2, int n) {
    __shared__ float sw[8][32][13];
    __shared__ int   si[8][32];
    int gwarp = (blockIdx.x * 256 + threadIdx.x) >> 5;
    int lane  = threadIdx.x & 31;
    int wib   = threadIdx.x >> 5;
    if (gwarp >= n) return;
    int g = blockIdx.y;
    const float* bias = (g == 0) ? b0 : (g == 1) ? b1 : b2;
    int d = g * n + gwarp;
    int beg = g_off[d], end = g_off[d + 1];

    const float* hd = g_h + (size_t)d * HROW;
    float ad_r[NH], aself_w[NH];
    #pragma unroll
    for (int h = 0; h < NH; h++) {
        ad_r[h]    = g_ad[(size_t)d * PAD + h];
        aself_w[h] = __expf(lrelu(hd[72 + h] + ad_r[h]));
    }
    int h1 = lane >> 3;
    int h2 = (lane + 32) >> 3;

    float dsum[NH];
    #pragma unroll
    for (int h = 0; h < NH; h++) dsum[h] = 0.f;

    float acc1a = aself_w[h1] * hd[lane],      acc1b = 0.f;
    float acc2a = aself_w[h2] * hd[lane + 32], acc2b = 0.f;
    float acc3a = (lane < 8) ? aself_w[8] * hd[lane + 64] : 0.f, acc3b = 0.f;

    for (int cbeg = beg; cbeg < end; cbeg += 32) {
        int ecnt = min(32, end - cbeg);
        float wv[NH];
        int s_mine = 0;
        if (lane < ecnt) {                       // lane-parallel: scores + exp
            s_mine = g_csr[cbeg + lane];
            const float* hs = g_h + (size_t)s_mine * HROW;
            float4 p0 = *(const float4*)(hs + 72);
            float4 p1 = *(const float4*)(hs + 76);
            float  a8 = hs[80];
            float asv[NH] = {p0.x, p0.y, p0.z, p0.w, p1.x, p1.y, p1.z, p1.w, a8};
            #pragma unroll
            for (int h = 0; h < NH; h++) {
                wv[h] = __expf(lrelu(asv[h] + ad_r[h]));
                dsum[h] += wv[h];
            }
        } else {
            #pragma unroll
            for (int h = 0; h < NH; h++) wv[h] = 0.f;
        }
        #pragma unroll
        for (int h = 0; h < NH; h++) sw[wib][lane][h] = wv[h];
        si[wib][lane] = s_mine;
        __syncwarp();

        // feature-parallel sweep, 4 edges/iter, loads batched up front
        int j = 0;
        for (; j + 4 <= ecnt; j += 4) {
            const float* p0 = g_h + (size_t)si[wib][j + 0] * HROW;
            const float* p1 = g_h + (size_t)si[wib][j + 1] * HROW;
            const float* p2 = g_h + (size_t)si[wib][j + 2] * HROW;
            const float* p3 = g_h + (size_t)si[wib][j + 3] * HROW;
            float a0 = p0[lane],      a1 = p1[lane],      a2 = p2[lane],      a3 = p3[lane];
            float c0 = p0[lane + 32], c1 = p1[lane + 32], c2 = p2[lane + 32], c3 = p3[lane + 32];
            float e0 = 0.f, e1 = 0.f, e2 = 0.f, e3 = 0.f;
            if (lane < 8) {
                e0 = p0[lane + 64]; e1 = p1[lane + 64];
                e2 = p2[lane + 64]; e3 = p3[lane + 64];
            }
            float w10 = sw[wib][j + 0][h1], w11 = sw[wib][j + 1][h1];
            float w12 = sw[wib][j + 2][h1], w13 = sw[wib][j + 3][h1];
            float w20 = sw[wib][j + 0][h2], w21 = sw[wib][j + 1][h2];
            float w22 = sw[wib][j + 2][h2], w23 = sw[wib][j + 3][h2];
            acc1a += w10 * a0; acc1b += w11 * a1;
            acc1a += w12 * a2; acc1b += w13 * a3;
            acc2a += w20 * c0; acc2b += w21 * c1;
            acc2a += w22 * c2; acc2b += w23 * c3;
            if (lane < 8) {
                float w30 = sw[wib][j + 0][8], w31 = sw[wib][j + 1][8];
                float w32 = sw[wib][j + 2][8], w33 = sw[wib][j + 3][8];
                acc3a += w30 * e0; acc3b += w31 * e1;
                acc3a += w32 * e2; acc3b += w33 * e3;
            }
        }
        for (; j < ecnt; j++) {
            const float* p = g_h + (size_t)si[wib][j] * HROW;
            acc1a += sw[wib][j][h1] * p[lane];
            acc2a += sw[wib][j][h2] * p[lane + 32];
            if (lane < 8) acc3a += sw[wib][j][8] * p[lane + 64];
        }
        __syncwarp();
    }

    float acc1 = acc1a + acc1b, acc2 = acc2a + acc2b, acc3 = acc3a + acc3b;

    #pragma unroll
    for (int h = 0; h < NH; h++) {
        float v = dsum[h];
        #pragma unroll
        for (int ofs = 16; ofs; ofs >>= 1) v += __shfl_xor_sync(0xffffffffu, v, ofs);
        dsum[h] = v + aself_w[h];
    }

    float* orow = g_concat + (size_t)gwarp * (NG * HCc) + g * HCc;
    orow[lane]      = acc1 / (dsum[h1] + 1e-16f) + bias[lane];
    orow[lane + 32] = acc2 / (dsum[h2] + 1e-16f) + bias[lane + 32];
    if (lane < 8)
        orow[lane + 64] = acc3 / (dsum[8] + 1e-16f) + bias[lane + 64];
}

// ---------------- K4: relu -> [216,2] FNN -> softmax ----------------------------
__global__ void k_fnn(const float* __restrict__ fW, const float* __restrict__ fb,
                      float* __restrict__ out, int n) {
    __shared__ float Wl[NG * HCc * 2];
    int t = threadIdx.x;
    for (int i = t; i < NG * HCc * 2; i += blockDim.x) Wl[i] = fW[i];
    __syncthreads();
    int node = blockIdx.x * blockDim.x + t;
    if (node >= n) return;
    const float* row = g_concat + (size_t)node * (NG * HCc);
    float l0 = fb[0], l1 = fb[1];
    #pragma unroll 8
    for (int i = 0; i < NG * HCc; i++) {
        float v = row[i];
        v = v > 0.f ? v : 0.f;
        l0 += v * Wl[2 * i];
        l1 += v * Wl[2 * i + 1];
    }
    float mm = fmaxf(l0, l1);
    float e0 = __expf(l0 - mm), e1 = __expf(l1 - mm);
    float inv = 1.f / (e0 + e1);
    out[2 * node]     = e0 * inv;
    out[2 * node + 1] = e1 * inv;
}

// ---------------- host -----------------------------------------------------------
extern "C" void kernel_launch(void* const* d_in, const int* in_sizes, int n_in,
                              void* d_out, int out_size) {
    const float* x[3]   = {0, 0, 0};
    const int*   ei[3]  = {0, 0, 0};
    const float* W[3]   = {0, 0, 0};
    const float* asr[3] = {0, 0, 0};
    const float* adr[3] = {0, 0, 0};
    const float* b[3]   = {0, 0, 0};
    const float* fW = 0; const float* fb = 0;
    int ix = 0, ie = 0, iw = 0, cur = 0, c72 = 0;
    long long xsz = 0, esz = 0;

    for (int i = 0; i < n_in; i++) {
        long long sz = in_sizes[i];
        if (sz >= 1000000) {
            if (sz > 4000000) {
                if (ix < 3) { x[ix++] = (const float*)d_in[i]; xsz = sz; }
            } else {
                if (ie < 3) { ei[ie++] = (const int*)d_in[i]; esz = sz; }
            }
        } else if (sz == 128 * HCc) {
            if (iw < 3) { W[iw] = (const float*)d_in[i]; cur = iw; iw++; c72 = 0; }
        } else if (sz == HCc) {
            if (c72 == 0)      asr[cur] = (const float*)d_in[i];
            else if (c72 == 1) adr[cur] = (const float*)d_in[i];
            else               b[cur]   = (const float*)d_in[i];
            c72++;
        } else if (sz == NG * HCc * 2) {
            fW = (const float*)d_in[i];
        } else if (sz == 2) {
            fb = (const float*)d_in[i];
        }
    }

    int N = (int)(xsz / 128);
    int E = (int)(esz / 2);
    int n3 = NG * N, E3 = NG * E;
    float* out = (float*)d_out;

    dim3 gE((E + 255) / 256, NG);
    dim3 gLin((N + 63) / 64, NG);
    dim3 gSc((N * NH + 255) / 256, NG);
    dim3 gGat((N + 7) / 8, NG);
    int bN3 = (n3 + 255) / 256;
    int bE3 = (E3 + 255) / 256;
    int B = (n3 + SCAN_CHUNK - 1) / SCAN_CHUNK;

    k_detect      <<<1, 256>>>(ei[0], E);
    k_zero        <<<bN3, 256>>>(n3);
    k_convert_hist<<<gE, 256>>>(ei[0], ei[1], ei[2], E, N);
    k_scan_a      <<<B, 256>>>(n3);
    k_scan_b      <<<1, 256>>>(B);
    k_scan_c      <<<B, 256>>>(n3);
    k_fill        <<<bE3, 256>>>(E3);
    k_linear      <<<gLin, 288>>>(x[0], x[1], x[2], W[0], W[1], W[2], N);
    k_scores      <<<gSc, 256>>>(asr[0], asr[1], asr[2], adr[0], adr[1], adr[2], N);
    k_gat         <<<gGat, 256>>>(b[0], b[1], b[2], N);
    k_fnn         <<<(N + 255) / 256, 256>>>(fW, fb, out, N);
    (void)out_size;
}